// round 2
// baseline (speedup 1.0000x reference)
#include <cuda_runtime.h>
#include <math.h>
#include <stdint.h>

#define B_    8
#define CIN   256
#define COUT  256
#define HH    64
#define WW    64
#define HW    4096
#define K2    9
#define KTOT  (CIN * K2)   // 2304

typedef unsigned long long ull;

// Scratch: per (b, k, pixel): 4 corner indices + 4 corner weights (mask-premultiplied)
__device__ int   g_cidx[B_ * K2 * HW * 4];
__device__ float g_cwgt[B_ * K2 * HW * 4];
// Pre-transposed main weight: [kt = c*9+k][oc]
__device__ float g_wT[KTOT * COUT];

// ---------------- packed fp32x2 helpers (Blackwell dual-rate fp32) ----------------
__device__ __forceinline__ ull fma2(ull a, ull b, ull c) {
    ull d;
    asm("fma.rn.f32x2 %0, %1, %2, %3;" : "=l"(d) : "l"(a), "l"(b), "l"(c));
    return d;
}
__device__ __forceinline__ ull pack2(float lo, float hi) {
    ull r;
    asm("mov.b64 %0, {%1, %2};" : "=l"(r) : "f"(lo), "f"(hi));
    return r;
}
__device__ __forceinline__ void unpack2(ull v, float& lo, float& hi) {
    asm("mov.b64 {%0, %1}, %2;" : "=f"(lo), "=f"(hi) : "l"(v));
}
__device__ __forceinline__ void cpa16(uint32_t dst, const void* src) {
    asm volatile("cp.async.ca.shared.global [%0], [%1], 16;" :: "r"(dst), "l"(src));
}

// =====================================================================
// Kernel 0: transpose weight [COUT][KTOT] -> g_wT [KTOT][COUT]
// =====================================================================
__global__ void __launch_bounds__(256) transpose_w(const float* __restrict__ wgt)
{
    __shared__ float t[32][33];
    const int kt0 = blockIdx.x * 32;
    const int oc0 = blockIdx.y * 32;
    const int tx = threadIdx.x, ty = threadIdx.y;   // 32 x 8
#pragma unroll
    for (int r = ty; r < 32; r += 8)
        t[r][tx] = wgt[(size_t)(oc0 + r) * KTOT + kt0 + tx];
    __syncthreads();
#pragma unroll
    for (int r = ty; r < 32; r += 8)
        g_wT[(size_t)(kt0 + r) * COUT + oc0 + tx] = t[tx][r];
}

// =====================================================================
// Stage 1: offset(18ch) + mask(9ch) 3x3 conv, fused epilogue that emits
// bilinear corner indices/weights (weights premultiplied by the mask).
// =====================================================================
__global__ void __launch_bounds__(128) prep_kernel(
    const float* __restrict__ x,
    const float* __restrict__ offw, const float* __restrict__ offb,
    const float* __restrict__ modw, const float* __restrict__ modb)
{
    __shared__ float xs[10][18];     // (8+2) x (16+2) halo tile
    __shared__ float ws2[9 * 28];    // [k][oc padded to 28]

    const int b  = blockIdx.z;
    const int h0 = blockIdx.y * 8;
    const int w0 = blockIdx.x * 16;
    const int tid = threadIdx.x;
    const int th = tid >> 4, tw = tid & 15;
    const int h = h0 + th, w = w0 + tw;
    const float* xb = x + (size_t)b * CIN * HW;

    ull acc2[14];
#pragma unroll
    for (int i = 0; i < 14; i++) acc2[i] = 0ull;

    for (int c = 0; c < CIN; c++) {
        for (int i = tid; i < 180; i += 128) {
            int r = i / 18, cc = i - r * 18;
            int gh = h0 - 1 + r, gw = w0 - 1 + cc;
            float v = 0.f;
            if (gh >= 0 && gh < HH && gw >= 0 && gw < WW) v = xb[c * HW + gh * WW + gw];
            (&xs[0][0])[i] = v;
        }
        for (int i = tid; i < 252; i += 128) {
            int k = i / 28, oc = i - k * 28;
            float v;
            if (oc < 18)      v = offw[(oc * CIN + c) * 9 + k];
            else if (oc < 27) v = modw[((oc - 18) * CIN + c) * 9 + k];
            else              v = 0.f;
            ws2[i] = v;
        }
        __syncthreads();

        ull wd[9];
#pragma unroll
        for (int k = 0; k < 9; k++) {
            float v = xs[th + k / 3][tw + k % 3];
            wd[k] = pack2(v, v);
        }
#pragma unroll
        for (int k = 0; k < 9; k++) {
            const float* row = ws2 + k * 28;
#pragma unroll
            for (int u = 0; u < 7; u++) {
                ulonglong2 tt = *(const ulonglong2*)(row + u * 4);
                acc2[2 * u]     = fma2(wd[k], tt.x, acc2[2 * u]);
                acc2[2 * u + 1] = fma2(wd[k], tt.y, acc2[2 * u + 1]);
            }
        }
        __syncthreads();
    }

    float acc[28];
#pragma unroll
    for (int u = 0; u < 14; u++) unpack2(acc2[u], acc[2 * u], acc[2 * u + 1]);

    const int pix = h * WW + w;
#pragma unroll
    for (int k = 0; k < 9; k++) {
        float dy = acc[2 * k]     + offb[2 * k];
        float dx = acc[2 * k + 1] + offb[2 * k + 1];
        float mz = acc[18 + k]    + modb[k];
        float m  = 2.f / (1.f + expf(-mz));

        float py = dy + (float)(h - 1 + k / 3);
        float px = dx + (float)(w - 1 + (k % 3));
        float y0f = floorf(py), x0f = floorf(px);
        float ly = py - y0f, lx = px - x0f;
        int y0 = (int)y0f, x0 = (int)x0f;

        int4 id; float4 wt;
        {
            int yy = y0, xx = x0; float wv = (1.f - ly) * (1.f - lx);
            bool v = (yy >= 0) && (yy < HH) && (xx >= 0) && (xx < WW);
            id.x = min(max(yy, 0), HH - 1) * WW + min(max(xx, 0), WW - 1);
            wt.x = v ? wv * m : 0.f;
        }
        {
            int yy = y0, xx = x0 + 1; float wv = (1.f - ly) * lx;
            bool v = (yy >= 0) && (yy < HH) && (xx >= 0) && (xx < WW);
            id.y = min(max(yy, 0), HH - 1) * WW + min(max(xx, 0), WW - 1);
            wt.y = v ? wv * m : 0.f;
        }
        {
            int yy = y0 + 1, xx = x0; float wv = ly * (1.f - lx);
            bool v = (yy >= 0) && (yy < HH) && (xx >= 0) && (xx < WW);
            id.z = min(max(yy, 0), HH - 1) * WW + min(max(xx, 0), WW - 1);
            wt.z = v ? wv * m : 0.f;
        }
        {
            int yy = y0 + 1, xx = x0 + 1; float wv = ly * lx;
            bool v = (yy >= 0) && (yy < HH) && (xx >= 0) && (xx < WW);
            id.w = min(max(yy, 0), HH - 1) * WW + min(max(xx, 0), WW - 1);
            wt.w = v ? wv * m : 0.f;
        }
        int slot = (b * K2 + k) * HW + pix;
        ((int4*)g_cidx)[slot]   = id;
        ((float4*)g_cwgt)[slot] = wt;
    }
}

// =====================================================================
// Stage 2: fused im2col + GEMM, software-pipelined:
//   - W tile (next chunk) filled via cp.async from pre-transposed g_wT
//   - gather corners (next chunk) prefetched into registers
//   - both overlap the FFMA2 GEMM of the current chunk
// Block = 64 pixels x 256 ocs; K-chunks of 4 channels x 9 taps = 36.
// =====================================================================
#define KC  36
// smem layout (floats)
#define SM_SAMPW 0
#define SM_SAMPI 2304
#define SM_S0    4608
#define SM_S1    9216
#define SM_W0    13824
#define SM_W1    23040
#define SMEM_FLOATS 32256          // 129024 bytes

__global__ void __launch_bounds__(256) dconv_kernel(
    const float* __restrict__ x,
    const float* __restrict__ bias, float* __restrict__ out)
{
    extern __shared__ float sm[];
    float* sampW = sm + SM_SAMPW;
    int*   sampI = (int*)(sm + SM_SAMPI);
    float* Sb[2] = { sm + SM_S0, sm + SM_S1 };
    float* Wb[2] = { sm + SM_W0, sm + SM_W1 };
    uint32_t Wb_u32[2] = {
        (uint32_t)__cvta_generic_to_shared(sm + SM_W0),
        (uint32_t)__cvta_generic_to_shared(sm + SM_W1)
    };

    const int b = blockIdx.z;
    const int pixbase = blockIdx.x * 64;
    const int tid = threadIdx.x;
    const int L   = tid & 7;            // pixel lane
    const int oc0 = (tid >> 3) * 8;     // 8 output channels / thread
    const float* xb = x + (size_t)b * CIN * HW;

    // cache sampling tables for this block's 64 pixels
    for (int i = tid; i < 576; i += 256) {
        int k = i >> 6, pix = i & 63;
        int slot = (b * K2 + k) * HW + pixbase + pix;
        ((float4*)sampW)[i] = ((const float4*)g_cwgt)[slot];
        ((int4*)sampI)[i]   = ((const int4*)g_cidx)[slot];
    }

    ull acc2[32];     // [pixel-slot pj=q*2+j][oc-pair o2]
#pragma unroll
    for (int o2 = 0; o2 < 4; o2++) {
        float2 bb = *(const float2*)(bias + oc0 + 2 * o2);
        ull bv = pack2(bb.x, bb.y);
#pragma unroll
        for (int pj = 0; pj < 8; pj++) acc2[pj * 4 + o2] = bv;
    }

    __syncthreads();   // samp tables visible before first prefetch

    float pre[36];

    // ---- stage chunk 0 ----
    {
        // W tile 0 via cp.async
        const float* wsrc = g_wT;            // chunk 0 -> rows 0..35
#pragma unroll
        for (int t = 0; t < 9; t++) {
            int j = tid + t * 256;
            cpa16(Wb_u32[0] + j * 16, wsrc + j * 4);
        }
        asm volatile("cp.async.commit_group;" ::: "memory");
        // gather prefetch for chunk 0
#pragma unroll
        for (int r = 0; r < 9; r++) {
            int i = tid + r * 256;
            int kk = i >> 6, pix = i & 63;
            int cidx = kk / 9, k = kk - cidx * 9;
            int si = (k << 6) + pix;
            int4 i4 = ((const int4*)sampI)[si];
            const float* xp = xb + cidx * HW;
            pre[4 * r + 0] = xp[i4.x];
            pre[4 * r + 1] = xp[i4.y];
            pre[4 * r + 2] = xp[i4.z];
            pre[4 * r + 3] = xp[i4.w];
        }
        // combine -> S0
#pragma unroll
        for (int r = 0; r < 9; r++) {
            int i = tid + r * 256;
            int kk = i >> 6, pix = i & 63;
            int cidx = kk / 9, k = kk - cidx * 9;
            int si = (k << 6) + pix;
            float4 w4 = ((const float4*)sampW)[si];
            float v = w4.x * pre[4 * r + 0] + w4.y * pre[4 * r + 1]
                    + w4.z * pre[4 * r + 2] + w4.w * pre[4 * r + 3];
            *(float2*)(Sb[0] + kk * 128 + pix * 2) = make_float2(v, v);
        }
        asm volatile("cp.async.wait_group 0;" ::: "memory");
    }
    __syncthreads();

    for (int c = 0; c < 64; c++) {
        const int cur = c & 1;
        const int nxt = cur ^ 1;

        if (c < 63) {
            // cp.async next W tile
            const float* wsrc = g_wT + (size_t)(c + 1) * 9216;
#pragma unroll
            for (int t = 0; t < 9; t++) {
                int j = tid + t * 256;
                cpa16(Wb_u32[nxt] + j * 16, wsrc + j * 4);
            }
            asm volatile("cp.async.commit_group;" ::: "memory");
            // prefetch next chunk gathers
            const float* xc = xb + (size_t)(c + 1) * 4 * HW;
#pragma unroll
            for (int r = 0; r < 9; r++) {
                int i = tid + r * 256;
                int kk = i >> 6, pix = i & 63;
                int cidx = kk / 9, k = kk - cidx * 9;
                int si = (k << 6) + pix;
                int4 i4 = ((const int4*)sampI)[si];
                const float* xp = xc + cidx * HW;
                pre[4 * r + 0] = xp[i4.x];
                pre[4 * r + 1] = xp[i4.y];
                pre[4 * r + 2] = xp[i4.z];
                pre[4 * r + 3] = xp[i4.w];
            }
        }

        // ---- GEMM on current buffers ----
        const float* Scur = Sb[cur];
        const float* Wcur = Wb[cur];
#pragma unroll 6
        for (int kk = 0; kk < KC; kk++) {
            const float* wrow = Wcur + kk * 256 + oc0;
            ulonglong2 b01 = *(const ulonglong2*)(wrow);
            ulonglong2 b23 = *(const ulonglong2*)(wrow + 4);
            ull bf0 = b01.x, bf1 = b01.y, bf2 = b23.x, bf3 = b23.y;
            const float* srow = Scur + kk * 128 + L * 4;
#pragma unroll
            for (int q = 0; q < 4; q++) {
                ulonglong2 av = *(const ulonglong2*)(srow + q * 32);
                int i0 = (q * 2) * 4, i1 = (q * 2 + 1) * 4;
                acc2[i0 + 0] = fma2(av.x, bf0, acc2[i0 + 0]);
                acc2[i0 + 1] = fma2(av.x, bf1, acc2[i0 + 1]);
                acc2[i0 + 2] = fma2(av.x, bf2, acc2[i0 + 2]);
                acc2[i0 + 3] = fma2(av.x, bf3, acc2[i0 + 3]);
                acc2[i1 + 0] = fma2(av.y, bf0, acc2[i1 + 0]);
                acc2[i1 + 1] = fma2(av.y, bf1, acc2[i1 + 1]);
                acc2[i1 + 2] = fma2(av.y, bf2, acc2[i1 + 2]);
                acc2[i1 + 3] = fma2(av.y, bf3, acc2[i1 + 3]);
            }
        }

        if (c < 63) {
            // combine prefetched corners into next S tile
            float* Sn = Sb[nxt];
#pragma unroll
            for (int r = 0; r < 9; r++) {
                int i = tid + r * 256;
                int kk = i >> 6, pix = i & 63;
                int cidx = kk / 9, k = kk - cidx * 9;
                int si = (k << 6) + pix;
                float4 w4 = ((const float4*)sampW)[si];
                float v = w4.x * pre[4 * r + 0] + w4.y * pre[4 * r + 1]
                        + w4.z * pre[4 * r + 2] + w4.w * pre[4 * r + 3];
                *(float2*)(Sn + kk * 128 + pix * 2) = make_float2(v, v);
            }
            asm volatile("cp.async.wait_group 0;" ::: "memory");
        }
        __syncthreads();
    }

    // epilogue
    float* ob = out + (size_t)b * COUT * HW + pixbase;
#pragma unroll
    for (int q = 0; q < 4; q++)
#pragma unroll
        for (int j = 0; j < 2; j++) {
            int p = q * 16 + L * 2 + j;
#pragma unroll
            for (int o2 = 0; o2 < 4; o2++) {
                float lo, hi;
                unpack2(acc2[(q * 2 + j) * 4 + o2], lo, hi);
                int oc = oc0 + 2 * o2;
                ob[(size_t)oc * HW + p]       = lo;
                ob[(size_t)(oc + 1) * HW + p] = hi;
            }
        }
}

extern "C" void kernel_launch(void* const* d_in, const int* in_sizes, int n_in,
                              void* d_out, int out_size)
{
    const float* x    = (const float*)d_in[0];
    const float* offw = (const float*)d_in[1];
    const float* offb = (const float*)d_in[2];
    const float* modw = (const float*)d_in[3];
    const float* modb = (const float*)d_in[4];
    const float* wgt  = (const float*)d_in[5];
    const float* bias = (const float*)d_in[6];
    float* out = (float*)d_out;

    cudaFuncSetAttribute(dconv_kernel, cudaFuncAttributeMaxDynamicSharedMemorySize,
                         SMEM_FLOATS * 4);

    dim3 gt(KTOT / 32, COUT / 32);
    transpose_w<<<gt, dim3(32, 8)>>>(wgt);

    dim3 g1(4, 8, 8);       // w-tiles, h-tiles, batch
    prep_kernel<<<g1, 128>>>(x, offw, offb, modw, modb);

    dim3 g2(64, 1, 8);      // one 64-pixel row per block, batch
    dconv_kernel<<<g2, 256, SMEM_FLOATS * 4>>>(x, bias, out);
}